// round 2
// baseline (speedup 1.0000x reference)
#include <cuda_runtime.h>
#include <cuda_bf16.h>

#define N_NODES 100000
#define N_EDGES 3200000
#define F_IN 35
#define F_HID 64
#define F_OUT 2

// Scratch (static __device__ arrays; allocation inside kernel_launch is forbidden)
__device__ __align__(16) float g_h1[N_NODES * F_HID];     // x @ W1
__device__ __align__(16) float g_agg1[N_NODES * F_HID];   // aggregated layer-1 (pre-bias/relu)
__device__ __align__(16) float g_deg[N_NODES];
__device__ __align__(16) float g_dinv[N_NODES];
__device__ __align__(16) float g_h2[N_NODES * F_OUT];     // relu(agg1+b1) @ W2
__device__ __align__(16) float g_agg2[N_NODES * F_OUT];

// ---------------- degree ----------------
__global__ void k_deg_init(int n) {
    int i = blockIdx.x * blockDim.x + threadIdx.x;
    if (i < n) g_deg[i] = 1.0f;  // self-loop weight 1
}

__global__ void k_deg_scatter(const int* __restrict__ ei,
                              const float* __restrict__ ew, int ne) {
    int e = blockIdx.x * blockDim.x + threadIdx.x;
    if (e >= ne) return;
    int dst = ei[ne + e];
    atomicAdd(&g_deg[dst], ew[e]);
}

__global__ void k_dinv(int n) {
    int i = blockIdx.x * blockDim.x + threadIdx.x;
    if (i < n) {
        float d = g_deg[i];
        g_dinv[i] = (d > 0.0f) ? rsqrtf(d) : 0.0f;
    }
}

// ---------------- layer-1 GEMM: h1 = x@W1, agg1 init = dinv^2 * h1 ----------------
__global__ void k_gemm1(const float* __restrict__ x, const float* __restrict__ W1, int n) {
    __shared__ float sW[F_IN * F_HID];  // 35*64
    __shared__ float sx[8][F_IN + 1];
    int t = threadIdx.x;
    for (int i = t; i < F_IN * F_HID; i += 256) sW[i] = W1[i];
    int w = t >> 5, lane = t & 31;
    int row = blockIdx.x * 8 + w;
    if (row < n) {
        sx[w][lane] = x[row * F_IN + lane];               // lanes 0..31 -> k 0..31
        if (lane < F_IN - 32) sx[w][32 + lane] = x[row * F_IN + 32 + lane];
    }
    __syncthreads();
    if (row >= n) return;
    float acc0 = 0.f, acc1 = 0.f;
#pragma unroll
    for (int k = 0; k < F_IN; k++) {
        float xv = sx[w][k];
        acc0 += xv * sW[k * F_HID + lane];
        acc1 += xv * sW[k * F_HID + lane + 32];
    }
    float dv = g_dinv[row];
    float sl = dv * dv;  // self-loop norm
    g_h1[row * F_HID + lane]        = acc0;
    g_h1[row * F_HID + lane + 32]   = acc1;
    g_agg1[row * F_HID + lane]      = sl * acc0;
    g_agg1[row * F_HID + lane + 32] = sl * acc1;
}

// ---------------- layer-1 edge scatter: 16 lanes per edge, red.v4 ----------------
__global__ void k_scatter1(const int* __restrict__ ei,
                           const float* __restrict__ ew, int ne) {
    int tid = blockIdx.x * blockDim.x + threadIdx.x;
    int e = tid >> 4;
    int lane = tid & 15;
    if (e >= ne) return;
    int src = ei[e];
    int dst = ei[ne + e];
    float norm = g_dinv[src] * ew[e] * g_dinv[dst];
    const float4 v = *reinterpret_cast<const float4*>(g_h1 + (size_t)src * F_HID + lane * 4);
    float mx = v.x * norm, my = v.y * norm, mz = v.z * norm, mw = v.w * norm;
    float* p = g_agg1 + (size_t)dst * F_HID + lane * 4;
    asm volatile("red.global.add.v4.f32 [%0], {%1, %2, %3, %4};"
                 :: "l"(p), "f"(mx), "f"(my), "f"(mz), "f"(mw) : "memory");
}

// ---------------- layer-2: relu(agg1+b1) @ W2, agg2 init ----------------
__global__ void k_layer2(const float* __restrict__ W2, const float* __restrict__ b1, int n) {
    int w = (blockIdx.x * blockDim.x + threadIdx.x) >> 5;
    int lane = threadIdx.x & 31;
    if (w >= n) return;
    float h0 = fmaxf(g_agg1[(size_t)w * F_HID + lane]      + b1[lane],      0.f);
    float h1 = fmaxf(g_agg1[(size_t)w * F_HID + lane + 32] + b1[lane + 32], 0.f);
    float p0 = h0 * W2[lane * 2 + 0] + h1 * W2[(lane + 32) * 2 + 0];
    float p1 = h0 * W2[lane * 2 + 1] + h1 * W2[(lane + 32) * 2 + 1];
#pragma unroll
    for (int o = 16; o > 0; o >>= 1) {
        p0 += __shfl_xor_sync(0xFFFFFFFFu, p0, o);
        p1 += __shfl_xor_sync(0xFFFFFFFFu, p1, o);
    }
    if (lane == 0) {
        float dv = g_dinv[w];
        float sl = dv * dv;
        g_h2[w * 2 + 0] = p0;
        g_h2[w * 2 + 1] = p1;
        g_agg2[w * 2 + 0] = sl * p0;
        g_agg2[w * 2 + 1] = sl * p1;
    }
}

// ---------------- layer-2 edge scatter: 1 thread per edge, red.v2 ----------------
__global__ void k_scatter2(const int* __restrict__ ei,
                           const float* __restrict__ ew, int ne) {
    int e = blockIdx.x * blockDim.x + threadIdx.x;
    if (e >= ne) return;
    int src = ei[e];
    int dst = ei[ne + e];
    float norm = g_dinv[src] * ew[e] * g_dinv[dst];
    float2 v = *reinterpret_cast<const float2*>(g_h2 + src * 2);
    float* p = g_agg2 + dst * 2;
    asm volatile("red.global.add.v2.f32 [%0], {%1, %2};"
                 :: "l"(p), "f"(v.x * norm), "f"(v.y * norm) : "memory");
}

// ---------------- output: bias + log_softmax ----------------
__global__ void k_out(const float* __restrict__ b2, float* __restrict__ out, int n) {
    int i = blockIdx.x * blockDim.x + threadIdx.x;
    if (i >= n) return;
    float a = g_agg2[i * 2 + 0] + b2[0];
    float b = g_agg2[i * 2 + 1] + b2[1];
    float m = fmaxf(a, b);
    float lse = m + logf(expf(a - m) + expf(b - m));
    out[i * 2 + 0] = a - lse;
    out[i * 2 + 1] = b - lse;
}

extern "C" void kernel_launch(void* const* d_in, const int* in_sizes, int n_in,
                              void* d_out, int out_size) {
    const float* x  = (const float*)d_in[0];
    const int*   ei = (const int*)d_in[1];   // int32! (JAX x64 disabled downcasts int64)
    const float* ew = (const float*)d_in[2];
    const float* W1 = (const float*)d_in[3];
    const float* b1 = (const float*)d_in[4];
    const float* W2 = (const float*)d_in[5];
    const float* b2 = (const float*)d_in[6];
    float* out = (float*)d_out;

    const int n  = in_sizes[0] / F_IN;   // 100000
    const int ne = in_sizes[2];          // 3200000

    k_deg_init<<<(n + 255) / 256, 256>>>(n);
    k_deg_scatter<<<(ne + 255) / 256, 256>>>(ei, ew, ne);
    k_dinv<<<(n + 255) / 256, 256>>>(n);
    k_gemm1<<<(n + 7) / 8, 256>>>(x, W1, n);
    {
        long long threads = (long long)ne * 16;
        k_scatter1<<<(unsigned)((threads + 255) / 256), 256>>>(ei, ew, ne);
    }
    k_layer2<<<(n * 32 + 255) / 256, 256>>>(W2, b1, n);
    k_scatter2<<<(ne + 255) / 256, 256>>>(ei, ew, ne);
    k_out<<<(n + 255) / 256, 256>>>(b2, out, n);
}